// round 15
// baseline (speedup 1.0000x reference)
#include <cuda_runtime.h>
#include <cuda_fp16.h>
#include <cstdint>

static constexpr int NT = 4096;   // tokens
static constexpr int DD = 1024;   // d_in == d_out
static constexpr size_t WW = (size_t)DD * DD;

// ---------------- scratch (__device__ globals: allocation-free rule) --------
__device__ float g_V[(size_t)NT * DD];              // fp32 V from prep epilogue
__device__ float g_S[(size_t)NT * NT];              // fp32 scores (sparse-written)

__device__ __half g_xh[(size_t)NT * DD], g_xl[(size_t)NT * DD];
// region 0: W~q hi | region 1: W~k hi | region 2: Wv^T hi
__device__ __half g_wh[(size_t)3 * DD * DD];
__device__ __half g_wl[(size_t)2 * DD * DD];        // lo for Wq (used), Wk (unused)
__device__ __half g_Th[(size_t)NT * DD];            // T~ = x@M~ (hi only)
__device__ __half g_MTh[(size_t)DD * DD];           // M~^T (hi only)
__device__ __half g_Ph[(size_t)NT * NT];            // P fp16

// rank-2 correction scalars
__device__ float g_aq[DD], g_ak[DD];
__device__ float g_rs[NT], g_xak[NT], g_c1[NT], g_c2[NT];
__device__ float g_rmc[NT];                         // per-row corr max (scaled)

// sparsity bookkeeping
__device__ int g_flags[32][64];                     // PV: rowblock x 64-chunk
__device__ int g_chunks[32][66];
__device__ int g_nchunk[32];
__device__ int g_sflags[32][32];                    // scores: rowblock x colblock(128)

// ---------------- helpers ---------------------------------------------------
__device__ __forceinline__ uint32_t smem_u32(const void* p) {
    uint32_t a;
    asm("{ .reg .u64 t; cvta.to.shared.u64 t, %1; cvt.u32.u64 %0, t; }"
        : "=r"(a) : "l"(p));
    return a;
}

#define SWZ(o) ((o) ^ ((((uint32_t)(o)) >> 3) & 0x70))

__device__ __forceinline__ void cp16(uint32_t saddr, const void* gaddr) {
    asm volatile("cp.async.cg.shared.global [%0], [%1], 16;"
                 :: "r"(saddr), "l"(gaddr));
}

__device__ __forceinline__ void ldm_x4(uint32_t* r, uint32_t addr) {
    asm volatile("ldmatrix.sync.aligned.m8n8.x4.shared.b16 {%0,%1,%2,%3}, [%4];"
                 : "=r"(r[0]), "=r"(r[1]), "=r"(r[2]), "=r"(r[3]) : "r"(addr));
}

__device__ __forceinline__ void mma_f16(float* c, const uint32_t* a, const uint32_t* b) {
    asm volatile(
        "mma.sync.aligned.m16n8k16.row.col.f32.f16.f16.f32 "
        "{%0,%1,%2,%3}, {%4,%5,%6,%7}, {%8,%9}, {%0,%1,%2,%3};"
        : "+f"(c[0]), "+f"(c[1]), "+f"(c[2]), "+f"(c[3])
        : "r"(a[0]), "r"(a[1]), "r"(a[2]), "r"(a[3]), "r"(b[0]), "r"(b[1]));
}

__device__ __forceinline__ void split_store_f16(
    __half* H, __half* L, size_t idx, float a, float b)
{
    const __half h0 = __float2half_rn(a);
    const __half h1 = __float2half_rn(b);
    const __half l0 = __float2half_rn(a - __half2float(h0));
    const __half l1 = __float2half_rn(b - __half2float(h1));
    *reinterpret_cast<__half2*>(H + idx) = __halves2half2(h0, h1);
    *reinterpret_cast<__half2*>(L + idx) = __halves2half2(l0, l1);
}

// ---------------------------------------------------------------------------
// Warp-MMA fp16 GEMM, BK=64, 3-stage cp.async pipeline.
//  MODE 0 (scores): S = Th@xh^T (1 term); occ 2; SPARSE tiles: prologue bound
//                   check vs g_rmc, inactive CTAs set sflag=0 and exit without
//                   computing or writing; epilogue adds rank-2 corr * alpha.
//  MODE 1 (PV):     C = Ph@Vth^T, 1 term, SPARSE over active K-chunks; occ 2.
//  MODE 2 (prep, fused grid; occ 1; tiles {A0,B0,B1}):
//     by <  32: V = xh @ Wvh^T (1 term) -> g_V fp32
//     by >= 32: M~^T = Wkh @ (Wqh + Wql)^T (2 terms) -> g_MTh (hi only)
//  MODE 3 (T):      T~ = xh@M~h (1 term) -> g_Th; occ 2.
// BM=BN=128, BK=64, 256 threads, 2(m)x4(n) warps, 64x32 warp tile.
// ---------------------------------------------------------------------------
static constexpr int TILE_B = 128 * 128;   // 16 KB (128 rows x 64 fp16)

template <int MODE>
__global__ __launch_bounds__(256, (MODE == 2) ? 1 : 2)
void gemm_mma(const __half* __restrict__ A0, const __half* __restrict__ B0,
              float* __restrict__ C, int M, int N, int K, float alpha)
{
    constexpr int NTILES  = (MODE == 2) ? 3 : 2;
    constexpr int STAGE_B = NTILES * TILE_B;

    extern __shared__ char smem[];
    const uint32_t sb = smem_u32(smem);
    const int tid  = threadIdx.x;
    const int wid  = tid >> 5;
    const int lane = tid & 31;

    const bool isM = (MODE == 2) && (blockIdx.y >= 32);   // M~^T region of prep
    const int bm = (MODE == 2 && isM) ? (blockIdx.y - 32) * 128 : blockIdx.y * 128;
    const int bn = blockIdx.x * 128;
    const int wm = (wid >> 2) * 64;
    const int wn = (wid & 3) * 32;

    // ---- MODE 0: sparse-tile prologue (bound check, maybe exit) ----
    if (MODE == 0) {
        __shared__ int s_act;
        if (tid == 0) s_act = 0;
        __syncthreads();
        const int i = bm + (tid & 127);
        const float c1 = g_c1[i] * alpha;
        const float c2 = g_c2[i] * alpha;
        const float thr = g_rmc[i] - 1240.0f;   // 20 + 2*600 margin + slack
        const int j0 = bn + (tid >> 7) * 64;
        bool found = false;
        for (int jj = 0; jj < 64; jj++) {
            if (c1 * g_rs[j0 + jj] + c2 * g_xak[j0 + jj] >= thr) { found = true; break; }
        }
        if (found) s_act = 1;
        __syncthreads();
        if (tid == 0) g_sflags[blockIdx.y][blockIdx.x] = s_act;
        if (!s_act) return;
    }

    const bool useB1 = (MODE == 2) && isM;   // a0*b1 term (M region only)

    const __half* srcs[3];
    int rbs[3];
    if (MODE == 2) {
        if (isM) {      // A0 = Wk hi, B0 = Wq hi, B1 = Wq lo (all centered)
            srcs[0] = g_wh + WW; srcs[1] = g_wh;          srcs[2] = g_wl;
        } else {        // A0 = xh, B0 = Wv^T hi
            srcs[0] = g_xh;      srcs[1] = g_wh + 2 * WW; srcs[2] = nullptr;
        }
        rbs[0] = bm; rbs[1] = bn; rbs[2] = bn;
    } else {
        srcs[0] = A0; rbs[0] = bm;
        srcs[1] = B0; rbs[1] = bn;
        srcs[2] = nullptr; rbs[2] = 0;
    }

    auto issue = [&](int stage, int kchunk) {
#pragma unroll
        for (int t = 0; t < NTILES; t++) {
            if (MODE == 2 && !isM && t == 2) continue;   // V region: no B1 tile
#pragma unroll
            for (int u = 0; u < 4; u++) {
                const int v = tid + 256 * u;            // 0..1023
                const int row = v >> 3, c16 = v & 7;
                const uint32_t o = (uint32_t)(row * 128 + c16 * 16);
                cp16(sb + stage * STAGE_B + t * TILE_B + SWZ(o),
                     srcs[t] + (size_t)(rbs[t] + row) * K + kchunk * 64 + c16 * 8);
            }
        }
        asm volatile("cp.async.commit_group;");
    };

    float acc[4][4][4];
#pragma unroll
    for (int i = 0; i < 4; i++)
#pragma unroll
        for (int j = 0; j < 4; j++)
#pragma unroll
            for (int r = 0; r < 4; r++) acc[i][j][r] = 0.0f;

    // chunk schedule: MODE 1 uses the sparse per-row-block list; others dense
    const int* cl = (MODE == 1) ? g_chunks[blockIdx.y] : nullptr;
    const int nc  = (MODE == 1) ? g_nchunk[blockIdx.y] : K / 64;

    issue(0, (MODE == 1) ? cl[0] : 0);
    issue(1, (MODE == 1) ? cl[1] : 1);

    const int arow   = lane & 15;
    const int achunk = lane >> 4;
    const int bsub   = lane >> 3;
    const int brow   = (lane & 7) + (bsub >> 1) * 8;
    const int bchunk = bsub & 1;

    for (int i = 0; i < nc; i++) {
        if (i < nc - 1) asm volatile("cp.async.wait_group 1;");
        else            asm volatile("cp.async.wait_group 0;");
        __syncthreads();

        if (i + 2 < nc) issue((i + 2) % 3, (MODE == 1) ? cl[i + 2] : i + 2);

        const uint32_t base = sb + (i % 3) * STAGE_B;
#pragma unroll
        for (int s = 0; s < 4; s++) {                  // 4 x k16 per BK=64 chunk
            uint32_t a0[4][4], b0r[4][2], b1r[4][2];
#pragma unroll
            for (int t = 0; t < 4; t++) {
                const uint32_t o =
                    (uint32_t)((wm + t * 16 + arow) * 128 + (s * 2 + achunk) * 16);
                ldm_x4(a0[t], base + SWZ(o));
            }
#pragma unroll
            for (int g = 0; g < 2; g++) {
                const uint32_t o =
                    (uint32_t)((wn + g * 16 + brow) * 128 + (s * 2 + bchunk) * 16);
                uint32_t r[4];
                ldm_x4(r, base + 1 * TILE_B + SWZ(o));
                b0r[2 * g][0] = r[0]; b0r[2 * g][1] = r[1];
                b0r[2 * g + 1][0] = r[2]; b0r[2 * g + 1][1] = r[3];
                if (useB1) {
                    ldm_x4(r, base + 2 * TILE_B + SWZ(o));
                    b1r[2 * g][0] = r[0]; b1r[2 * g][1] = r[1];
                    b1r[2 * g + 1][0] = r[2]; b1r[2 * g + 1][1] = r[3];
                }
            }
#pragma unroll
            for (int mt = 0; mt < 4; mt++)
#pragma unroll
                for (int nt = 0; nt < 4; nt++) {
                    mma_f16(acc[mt][nt], a0[mt], b0r[nt]);
                    if (useB1) mma_f16(acc[mt][nt], a0[mt], b1r[nt]);
                }
        }
    }

    // ---- epilogue ----
    const int r0 = bm + wm + (lane >> 2);
    const int c0 = wn + (lane & 3) * 2;

    if (MODE == 2) {
#pragma unroll
        for (int mt = 0; mt < 4; mt++)
#pragma unroll
            for (int nt = 0; nt < 4; nt++) {
                const int row = r0 + mt * 16;
                const int col = bn + c0 + nt * 8;
                const size_t i0 = (size_t)row * DD + col;
                const size_t i1 = (size_t)(row + 8) * DD + col;
                if (isM) {
                    *reinterpret_cast<__half2*>(g_MTh + i0) =
                        __floats2half2_rn(acc[mt][nt][0], acc[mt][nt][1]);
                    *reinterpret_cast<__half2*>(g_MTh + i1) =
                        __floats2half2_rn(acc[mt][nt][2], acc[mt][nt][3]);
                } else {
                    *reinterpret_cast<float2*>(g_V + i0) =
                        make_float2(acc[mt][nt][0], acc[mt][nt][1]);
                    *reinterpret_cast<float2*>(g_V + i1) =
                        make_float2(acc[mt][nt][2], acc[mt][nt][3]);
                }
            }
    } else if (MODE == 3) {
#pragma unroll
        for (int mt = 0; mt < 4; mt++)
#pragma unroll
            for (int nt = 0; nt < 4; nt++) {
                const int row = r0 + mt * 16;
                const int col = bn + c0 + nt * 8;
                *reinterpret_cast<__half2*>(g_Th + (size_t)row * DD + col) =
                    __floats2half2_rn(acc[mt][nt][0], acc[mt][nt][1]);
                *reinterpret_cast<__half2*>(g_Th + (size_t)(row + 8) * DD + col) =
                    __floats2half2_rn(acc[mt][nt][2], acc[mt][nt][3]);
            }
    } else if (MODE == 0) {
        // s_ij = (acc + rs_j*c1_i + xak_j*c2_i) * alpha
#pragma unroll
        for (int mt = 0; mt < 4; mt++) {
            const int row = r0 + mt * 16;
            const float c1a = g_c1[row],     c2a = g_c2[row];
            const float c1b = g_c1[row + 8], c2b = g_c2[row + 8];
#pragma unroll
            for (int nt = 0; nt < 4; nt++) {
                const int col = bn + c0 + nt * 8;
                const float rs0 = g_rs[col],  rs1 = g_rs[col + 1];
                const float xk0 = g_xak[col], xk1 = g_xak[col + 1];
                *reinterpret_cast<float2*>(C + (size_t)row * N + col) =
                    make_float2((acc[mt][nt][0] + rs0 * c1a + xk0 * c2a) * alpha,
                                (acc[mt][nt][1] + rs1 * c1a + xk1 * c2a) * alpha);
                *reinterpret_cast<float2*>(C + (size_t)(row + 8) * N + col) =
                    make_float2((acc[mt][nt][2] + rs0 * c1b + xk0 * c2b) * alpha,
                                (acc[mt][nt][3] + rs1 * c1b + xk1 * c2b) * alpha);
            }
        }
    } else {   // MODE 1
#pragma unroll
        for (int mt = 0; mt < 4; mt++)
#pragma unroll
            for (int nt = 0; nt < 4; nt++) {
                const int row = r0 + mt * 16;
                const int col = bn + c0 + nt * 8;
                *reinterpret_cast<float2*>(C + (size_t)row * N + col) =
                    make_float2(acc[mt][nt][0], acc[mt][nt][1]);
                *reinterpret_cast<float2*>(C + (size_t)(row + 8) * N + col) =
                    make_float2(acc[mt][nt][2], acc[mt][nt][3]);
            }
    }
}

// ---------------------------------------------------------------------------
// fused hi/lo fp16 splits: z=0 -> x; z=1 -> Wq-0.5; z=2 -> Wk-0.5
// ---------------------------------------------------------------------------
__global__ __launch_bounds__(256)
void split3_f16(const float* __restrict__ x, const float* __restrict__ wq,
                const float* __restrict__ wk)
{
    const int z = blockIdx.y;
    const float* in = (z == 0) ? x : (z == 1) ? wq : wk;
    __half* hi = (z == 0) ? g_xh : (z == 1) ? g_wh : g_wh + WW;
    __half* lo = (z == 0) ? g_xl : (z == 1) ? g_wl : g_wl + WW;
    const int n = (z == 0) ? NT * DD : DD * DD;
    const float bias = (z == 0) ? 0.0f : 0.5f;

    const int idx = (blockIdx.x * 256 + threadIdx.x) * 2;
    if (idx < n) {
        const float2 v = *reinterpret_cast<const float2*>(in + idx);
        split_store_f16(hi, lo, idx, v.x - bias, v.y - bias);
    }
}

// ---------------------------------------------------------------------------
// fp32 [R,C] -> transposed fp16 [C,R], hi only   (Wv -> Wv^T, V -> V^T)
// ---------------------------------------------------------------------------
__global__ __launch_bounds__(256)
void t_h16(const float* __restrict__ in, __half* __restrict__ oh, int R, int C)
{
    __shared__ float t[32][33];
    const int bx = blockIdx.x * 32, by = blockIdx.y * 32;
    const int tx = threadIdx.x & 31, ty = threadIdx.x >> 5;
#pragma unroll
    for (int j = 0; j < 32; j += 8)
        t[ty + j][tx] = in[(size_t)(by + ty + j) * C + bx + tx];
    __syncthreads();
#pragma unroll
    for (int j = 0; j < 32; j += 8) {
        const float v = t[tx][ty + j];
        oh[(size_t)(bx + ty + j) * R + by + tx] = __float2half_rn(v);
    }
}

// ---------------------------------------------------------------------------
// Correction scalars — fp32 warp-per-row, shuffle reductions.
// ---------------------------------------------------------------------------
__global__ __launch_bounds__(256)
void wrowsums(const float* __restrict__ wq, const float* __restrict__ wk)
{
    const int warp = blockIdx.x * 8 + (threadIdx.x >> 5);   // 0..2047
    const int lane = threadIdx.x & 31;
    const int r = warp & 1023;
    const bool isq = warp < 1024;
    const float* src = (isq ? wq : wk) + (size_t)r * DD;

    float s = 0.0f;
#pragma unroll
    for (int it = 0; it < 8; it++) {
        const float4 v = *reinterpret_cast<const float4*>(src + it * 128 + lane * 4);
        s += (v.x - 0.5f) + (v.y - 0.5f) + (v.z - 0.5f) + (v.w - 0.5f);
    }
#pragma unroll
    for (int o = 16; o > 0; o >>= 1) s += __shfl_xor_sync(0xFFFFFFFFu, s, o);
    if (lane == 0) (isq ? g_aq : g_ak)[r] = s;
}

__global__ __launch_bounds__(256)
void xscalars(const float* __restrict__ x)
{
    if (blockIdx.x < 8) {                       // zero PV flags (2048 ints)
        (&g_flags[0][0])[blockIdx.x * 256 + threadIdx.x] = 0;
    }

    const int warp = blockIdx.x * 8 + (threadIdx.x >> 5);   // 0..4095
    const int lane = threadIdx.x & 31;
    const float* p = x + (size_t)warp * DD;

    float s0 = 0.0f, s1 = 0.0f, s2 = 0.0f;
#pragma unroll
    for (int it = 0; it < 8; it++) {
        const int d = it * 128 + lane * 4;
        const float4 xv = *reinterpret_cast<const float4*>(p + d);
        const float4 aq = *reinterpret_cast<const float4*>(g_aq + d);
        const float4 ak = *reinterpret_cast<const float4*>(g_ak + d);
        s0 += xv.x + xv.y + xv.z + xv.w;
        s1 += xv.x * aq.x + xv.y * aq.y + xv.z * aq.z + xv.w * aq.w;
        s2 += xv.x * ak.x + xv.y * ak.y + xv.z * ak.z + xv.w * ak.w;
    }
#pragma unroll
    for (int o = 16; o > 0; o >>= 1) {
        s0 += __shfl_xor_sync(0xFFFFFFFFu, s0, o);
        s1 += __shfl_xor_sync(0xFFFFFFFFu, s1, o);
        s2 += __shfl_xor_sync(0xFFFFFFFFu, s2, o);
    }
    if (lane == 0) {
        g_rs[warp]  = s0;
        g_xak[warp] = s2;
        g_c1[warp]  = 256.0f * s0 + 0.5f * s1;
        g_c2[warp]  = 0.5f * s0;
    }
}

// ---------------------------------------------------------------------------
// Per-row max of the rank-2 correction (scaled by 1/32); 32 rows per block.
// ---------------------------------------------------------------------------
__global__ __launch_bounds__(256)
void rowmax_corr()
{
    __shared__ float srs[NT];
    __shared__ float sxk[NT];
    const int tid = threadIdx.x;
    for (int j = tid; j < NT; j += 256) { srs[j] = g_rs[j]; sxk[j] = g_xak[j]; }
    __syncthreads();

    const int r = blockIdx.x * 32 + (tid >> 3);
    const int sub = tid & 7;
    const float c1 = g_c1[r], c2 = g_c2[r];
    float m = -3e38f;
    for (int j = sub; j < NT; j += 8)
        m = fmaxf(m, c1 * srs[j] + c2 * sxk[j]);
#pragma unroll
    for (int o = 4; o > 0; o >>= 1)
        m = fmaxf(m, __shfl_xor_sync(0xFFFFFFFFu, m, o));
    if (sub == 0) g_rmc[r] = m * (1.0f / 32.0f);
}

// ---------------------------------------------------------------------------
// Row softmax -> P fp16; consults g_sflags (unwritten tiles = -inf); exp-skip;
// sets PV active-chunk flags.
// ---------------------------------------------------------------------------
__global__ __launch_bounds__(256)
void softmax_f16(const float* __restrict__ S, __half* __restrict__ Ph)
{
    const int row = blockIdx.x;
    const float* p = S + (size_t)row * NT;
    const int tid = threadIdx.x;
    const int base = tid * 16;
    const bool ld = g_sflags[row >> 7][tid >> 3] != 0;

    float v[16];
    if (ld) {
#pragma unroll
        for (int q = 0; q < 4; q++) {
            const float4 x4 = *reinterpret_cast<const float4*>(p + base + q * 4);
            v[q * 4 + 0] = x4.x; v[q * 4 + 1] = x4.y;
            v[q * 4 + 2] = x4.z; v[q * 4 + 3] = x4.w;
        }
    } else {
#pragma unroll
        for (int q = 0; q < 16; q++) v[q] = -1e30f;
    }

    __shared__ float red[256];
    float tmax = v[0];
#pragma unroll
    for (int q = 1; q < 16; q++) tmax = fmaxf(tmax, v[q]);
    red[tid] = tmax;
    __syncthreads();
#pragma unroll
    for (int s = 128; s > 0; s >>= 1) {
        if (tid < s) red[tid] = fmaxf(red[tid], red[tid + s]);
        __syncthreads();
    }
    const float m = red[0];
    __syncthreads();

    const float cut = m - 20.0f;
    const bool active = (tmax >= cut);

    if (active) g_flags[row >> 7][tid >> 2] = 1;   // idempotent; races benign

    float sum = 0.0f;
    if (active) {
#pragma unroll
        for (int q = 0; q < 16; q++) {
            v[q] = (v[q] >= cut) ? __expf(v[q] - m) : 0.0f;
            sum += v[q];
        }
    }
    red[tid] = sum;
    __syncthreads();
#pragma unroll
    for (int s = 128; s > 0; s >>= 1) {
        if (tid < s) red[tid] += red[tid + s];
        __syncthreads();
    }
    const float inv = 1.0f / red[0];

    __half* ph = Ph + (size_t)row * NT + base;
    if (active) {
#pragma unroll
        for (int q = 0; q < 8; q++) {
            *reinterpret_cast<__half2*>(ph + 2 * q) =
                __floats2half2_rn(v[2 * q] * inv, v[2 * q + 1] * inv);
        }
    } else {
        const __half2 z = __floats2half2_rn(0.0f, 0.0f);
#pragma unroll
        for (int q = 0; q < 8; q++)
            *reinterpret_cast<__half2*>(ph + 2 * q) = z;
    }
}

// ---------------------------------------------------------------------------
// Compact PV active-chunk flags into per-row-block lists (padded by 2).
// ---------------------------------------------------------------------------
__global__ __launch_bounds__(32)
void compact_chunks()
{
    const int r = blockIdx.x;
    if (threadIdx.x == 0) {
        int c = 0;
#pragma unroll
        for (int i = 0; i < 64; i++)
            if (g_flags[r][i]) g_chunks[r][c++] = i;
        g_nchunk[r] = c;
        const int pad = g_chunks[r][0];
        g_chunks[r][c] = pad;
        g_chunks[r][c + 1] = pad;
    }
}

// ---------------------------------------------------------------------------
// kernel_launch
// ---------------------------------------------------------------------------
extern "C" void kernel_launch(void* const* d_in, const int* in_sizes, int n_in,
                              void* d_out, int out_size)
{
    const float* x  = (const float*)d_in[0];
    const float* wq = (const float*)d_in[1];
    const float* wk = (const float*)d_in[2];
    const float* wv = (const float*)d_in[3];
    float* out = (float*)d_out;

    float *V, *S;
    __half *xh, *wh, *Th, *MTh, *Vth, *Ph;
    cudaGetSymbolAddress((void**)&V, g_V);
    cudaGetSymbolAddress((void**)&S, g_S);
    cudaGetSymbolAddress((void**)&xh, g_xh);
    cudaGetSymbolAddress((void**)&wh, g_wh);
    cudaGetSymbolAddress((void**)&Th, g_Th);
    cudaGetSymbolAddress((void**)&MTh, g_MTh);
    cudaGetSymbolAddress((void**)&Ph, g_Ph);
    cudaGetSymbolAddress((void**)&Vth, g_xl);   // V^T fp16 reuses g_xl (xl unused)

    static bool attr_done = false;
    if (!attr_done) {
        cudaFuncSetAttribute(gemm_mma<0>, cudaFuncAttributeMaxDynamicSharedMemorySize,
                             3 * 2 * TILE_B);
        cudaFuncSetAttribute(gemm_mma<1>, cudaFuncAttributeMaxDynamicSharedMemorySize,
                             3 * 2 * TILE_B);
        cudaFuncSetAttribute(gemm_mma<2>, cudaFuncAttributeMaxDynamicSharedMemorySize,
                             3 * 3 * TILE_B);
        cudaFuncSetAttribute(gemm_mma<3>, cudaFuncAttributeMaxDynamicSharedMemorySize,
                             3 * 2 * TILE_B);
        attr_done = true;
    }

    const dim3 blk(256);

    // 1) prep: splits + Wv^T hi transpose + correction scalars + row corr-max
    split3_f16<<<dim3(NT * DD / 512, 3), blk>>>(x, wq, wk);
    t_h16<<<dim3(DD / 32, DD / 32), blk>>>(wv, wh + 2 * WW, DD, DD);
    wrowsums<<<256, blk>>>(wq, wk);
    xscalars<<<512, blk>>>(x);
    rowmax_corr<<<128, blk>>>();

    // 2) fused prep GEMM: V = xh@Wvh^T (fp32) and M~^T = Wkh@W~q^T (2-term)
    gemm_mma<2><<<dim3(DD / 128, NT / 128 + DD / 128), blk, 3 * 3 * TILE_B>>>(
        nullptr, nullptr, nullptr, 0, DD, DD, 1.0f);

    // 3) V^T fp16 (hi only) into g_xl
    t_h16<<<dim3(DD / 32, NT / 32), blk>>>(V, (__half*)Vth, NT, DD);

    // 4) T~ = xh @ M~h  (1 term)
    gemm_mma<3><<<dim3(DD / 128, NT / 128), blk, 3 * 2 * TILE_B>>>(
        xh, MTh, nullptr, NT, DD, DD, 1.0f);

    // 5) scores (SPARSE tiles): S = (Th @ xh^T + rank-2 corr) / 32
    gemm_mma<0><<<dim3(NT / 128, NT / 128), blk, 3 * 2 * TILE_B>>>(
        Th, xh, S, NT, NT, DD, 1.0f / 32.0f);

    // 6) softmax (sflag-aware) -> P fp16 + PV chunk flags; compact lists
    softmax_f16<<<NT, blk>>>(S, Ph);
    compact_chunks<<<32, 32>>>();

    // 7) out = P @ V   (1-term; SPARSE chunks; occ 2; B = V^T [1024, 4096])
    gemm_mma<1><<<dim3(DD / 128, NT / 128), blk, 3 * 2 * TILE_B>>>(
        Ph, (const __half*)Vth, out, NT, DD, NT, 1.0f);
}

// round 16
// speedup vs baseline: 1.1419x; 1.1419x over previous
#include <cuda_runtime.h>
#include <cuda_fp16.h>
#include <cstdint>

static constexpr int NT = 4096;   // tokens
static constexpr int DD = 1024;   // d_in == d_out
static constexpr size_t WW = (size_t)DD * DD;

// ---------------- scratch (__device__ globals: allocation-free rule) --------
__device__ float g_V[(size_t)NT * DD];              // fp32 V from prep epilogue
__device__ float g_S[(size_t)NT * NT];              // fp32 scores

__device__ __half g_xh[(size_t)NT * DD], g_xl[(size_t)NT * DD];
// region 0: W~q hi | region 1: W~k hi | region 2: Wv^T hi
__device__ __half g_wh[(size_t)3 * DD * DD];
__device__ __half g_wl[(size_t)2 * DD * DD];        // lo for Wq (used by M), Wk (unused)
__device__ __half g_Th[(size_t)NT * DD];            // T~ = x@M~ (hi only)
__device__ __half g_MTh[(size_t)DD * DD];           // M~^T (hi only)
__device__ __half g_Ph[(size_t)NT * NT];            // P fp16

// rank-2 correction scalars
__device__ float g_aq[DD], g_ak[DD];
__device__ float g_rs[NT], g_xak[NT], g_c1[NT], g_c2[NT];

// sparse-PV chunk bookkeeping: 32 row-blocks x 64 K-chunks
__device__ int g_flags[32][64];
__device__ int g_chunks[32][66];
__device__ int g_nchunk[32];

// ---------------- helpers ---------------------------------------------------
__device__ __forceinline__ uint32_t smem_u32(const void* p) {
    uint32_t a;
    asm("{ .reg .u64 t; cvta.to.shared.u64 t, %1; cvt.u32.u64 %0, t; }"
        : "=r"(a) : "l"(p));
    return a;
}

#define SWZ(o) ((o) ^ ((((uint32_t)(o)) >> 3) & 0x70))

__device__ __forceinline__ void cp16(uint32_t saddr, const void* gaddr) {
    asm volatile("cp.async.cg.shared.global [%0], [%1], 16;"
                 :: "r"(saddr), "l"(gaddr));
}

__device__ __forceinline__ void ldm_x4(uint32_t* r, uint32_t addr) {
    asm volatile("ldmatrix.sync.aligned.m8n8.x4.shared.b16 {%0,%1,%2,%3}, [%4];"
                 : "=r"(r[0]), "=r"(r[1]), "=r"(r[2]), "=r"(r[3]) : "r"(addr));
}

__device__ __forceinline__ void mma_f16(float* c, const uint32_t* a, const uint32_t* b) {
    asm volatile(
        "mma.sync.aligned.m16n8k16.row.col.f32.f16.f16.f32 "
        "{%0,%1,%2,%3}, {%4,%5,%6,%7}, {%8,%9}, {%0,%1,%2,%3};"
        : "+f"(c[0]), "+f"(c[1]), "+f"(c[2]), "+f"(c[3])
        : "r"(a[0]), "r"(a[1]), "r"(a[2]), "r"(a[3]), "r"(b[0]), "r"(b[1]));
}

__device__ __forceinline__ void split_store_f16(
    __half* H, __half* L, size_t idx, float a, float b)
{
    const __half h0 = __float2half_rn(a);
    const __half h1 = __float2half_rn(b);
    const __half l0 = __float2half_rn(a - __half2float(h0));
    const __half l1 = __float2half_rn(b - __half2float(h1));
    *reinterpret_cast<__half2*>(H + idx) = __halves2half2(h0, h1);
    *reinterpret_cast<__half2*>(L + idx) = __halves2half2(l0, l1);
}

// ---------------------------------------------------------------------------
// Warp-MMA fp16 GEMM, BK=64, 3-stage cp.async pipeline.
//  MODE 0 (scores): S = Th@xh^T (1 term, dense); occ 2;
//                   epilogue adds rank-2 correction, scales by alpha; fp32 C.
//  MODE 1 (PV):     C = Ph@Vth^T, 1 term, SPARSE over active K-chunks; occ 2.
//  MODE 2 (prep, fused grid; occ 1; tiles {A0,B0,B1}):
//     by <  32: V = xh @ Wvh^T (1 term) -> g_V fp32
//     by >= 32: M~^T = Wkh @ (Wqh + Wql)^T (2 terms) -> g_MTh (hi only)
//  MODE 3 (T):      T~ = xh@M~h (1 term) -> g_Th; occ 2.
// BM=BN=128, BK=64, 256 threads, 2(m)x4(n) warps, 64x32 warp tile.
// ---------------------------------------------------------------------------
static constexpr int TILE_B = 128 * 128;   // 16 KB (128 rows x 64 fp16)

template <int MODE>
__global__ __launch_bounds__(256, (MODE == 2) ? 1 : 2)
void gemm_mma(const __half* __restrict__ A0, const __half* __restrict__ B0,
              float* __restrict__ C, int M, int N, int K, float alpha)
{
    constexpr int NTILES  = (MODE == 2) ? 3 : 2;
    constexpr int STAGE_B = NTILES * TILE_B;

    extern __shared__ char smem[];
    const uint32_t sb = smem_u32(smem);
    const int tid  = threadIdx.x;
    const int wid  = tid >> 5;
    const int lane = tid & 31;

    const bool isM = (MODE == 2) && (blockIdx.y >= 32);   // M~^T region of prep
    const int bm = (MODE == 2 && isM) ? (blockIdx.y - 32) * 128 : blockIdx.y * 128;
    const int bn = blockIdx.x * 128;
    const int wm = (wid >> 2) * 64;
    const int wn = (wid & 3) * 32;

    const bool useB1 = (MODE == 2) && isM;   // a0*b1 term (M region only)

    const __half* srcs[3];
    int rbs[3];
    if (MODE == 2) {
        if (isM) {      // A0 = Wk hi, B0 = Wq hi, B1 = Wq lo (all centered)
            srcs[0] = g_wh + WW; srcs[1] = g_wh;          srcs[2] = g_wl;
        } else {        // A0 = xh, B0 = Wv^T hi
            srcs[0] = g_xh;      srcs[1] = g_wh + 2 * WW; srcs[2] = nullptr;
        }
        rbs[0] = bm; rbs[1] = bn; rbs[2] = bn;
    } else {
        srcs[0] = A0; rbs[0] = bm;
        srcs[1] = B0; rbs[1] = bn;
        srcs[2] = nullptr; rbs[2] = 0;
    }

    auto issue = [&](int stage, int kchunk) {
#pragma unroll
        for (int t = 0; t < NTILES; t++) {
            if (MODE == 2 && !isM && t == 2) continue;   // V region: no B1 tile
#pragma unroll
            for (int u = 0; u < 4; u++) {
                const int v = tid + 256 * u;            // 0..1023
                const int row = v >> 3, c16 = v & 7;
                const uint32_t o = (uint32_t)(row * 128 + c16 * 16);
                cp16(sb + stage * STAGE_B + t * TILE_B + SWZ(o),
                     srcs[t] + (size_t)(rbs[t] + row) * K + kchunk * 64 + c16 * 8);
            }
        }
        asm volatile("cp.async.commit_group;");
    };

    float acc[4][4][4];
#pragma unroll
    for (int i = 0; i < 4; i++)
#pragma unroll
        for (int j = 0; j < 4; j++)
#pragma unroll
            for (int r = 0; r < 4; r++) acc[i][j][r] = 0.0f;

    // chunk schedule: MODE 1 uses the sparse per-row-block list; others dense
    const int* cl = (MODE == 1) ? g_chunks[blockIdx.y] : nullptr;
    const int nc  = (MODE == 1) ? g_nchunk[blockIdx.y] : K / 64;

    issue(0, (MODE == 1) ? cl[0] : 0);
    issue(1, (MODE == 1) ? cl[1] : 1);

    const int arow   = lane & 15;
    const int achunk = lane >> 4;
    const int bsub   = lane >> 3;
    const int brow   = (lane & 7) + (bsub >> 1) * 8;
    const int bchunk = bsub & 1;

    for (int i = 0; i < nc; i++) {
        if (i < nc - 1) asm volatile("cp.async.wait_group 1;");
        else            asm volatile("cp.async.wait_group 0;");
        __syncthreads();

        if (i + 2 < nc) issue((i + 2) % 3, (MODE == 1) ? cl[i + 2] : i + 2);

        const uint32_t base = sb + (i % 3) * STAGE_B;
#pragma unroll
        for (int s = 0; s < 4; s++) {                  // 4 x k16 per BK=64 chunk
            uint32_t a0[4][4], b0r[4][2], b1r[4][2];
#pragma unroll
            for (int t = 0; t < 4; t++) {
                const uint32_t o =
                    (uint32_t)((wm + t * 16 + arow) * 128 + (s * 2 + achunk) * 16);
                ldm_x4(a0[t], base + SWZ(o));
            }
#pragma unroll
            for (int g = 0; g < 2; g++) {
                const uint32_t o =
                    (uint32_t)((wn + g * 16 + brow) * 128 + (s * 2 + bchunk) * 16);
                uint32_t r[4];
                ldm_x4(r, base + 1 * TILE_B + SWZ(o));
                b0r[2 * g][0] = r[0]; b0r[2 * g][1] = r[1];
                b0r[2 * g + 1][0] = r[2]; b0r[2 * g + 1][1] = r[3];
                if (useB1) {
                    ldm_x4(r, base + 2 * TILE_B + SWZ(o));
                    b1r[2 * g][0] = r[0]; b1r[2 * g][1] = r[1];
                    b1r[2 * g + 1][0] = r[2]; b1r[2 * g + 1][1] = r[3];
                }
            }
#pragma unroll
            for (int mt = 0; mt < 4; mt++)
#pragma unroll
                for (int nt = 0; nt < 4; nt++) {
                    mma_f16(acc[mt][nt], a0[mt], b0r[nt]);
                    if (useB1) mma_f16(acc[mt][nt], a0[mt], b1r[nt]);
                }
        }
    }

    // ---- epilogue ----
    const int r0 = bm + wm + (lane >> 2);
    const int c0 = wn + (lane & 3) * 2;

    if (MODE == 2) {
#pragma unroll
        for (int mt = 0; mt < 4; mt++)
#pragma unroll
            for (int nt = 0; nt < 4; nt++) {
                const int row = r0 + mt * 16;
                const int col = bn + c0 + nt * 8;
                const size_t i0 = (size_t)row * DD + col;
                const size_t i1 = (size_t)(row + 8) * DD + col;
                if (isM) {
                    *reinterpret_cast<__half2*>(g_MTh + i0) =
                        __floats2half2_rn(acc[mt][nt][0], acc[mt][nt][1]);
                    *reinterpret_cast<__half2*>(g_MTh + i1) =
                        __floats2half2_rn(acc[mt][nt][2], acc[mt][nt][3]);
                } else {
                    *reinterpret_cast<float2*>(g_V + i0) =
                        make_float2(acc[mt][nt][0], acc[mt][nt][1]);
                    *reinterpret_cast<float2*>(g_V + i1) =
                        make_float2(acc[mt][nt][2], acc[mt][nt][3]);
                }
            }
    } else if (MODE == 3) {
#pragma unroll
        for (int mt = 0; mt < 4; mt++)
#pragma unroll
            for (int nt = 0; nt < 4; nt++) {
                const int row = r0 + mt * 16;
                const int col = bn + c0 + nt * 8;
                *reinterpret_cast<__half2*>(g_Th + (size_t)row * DD + col) =
                    __floats2half2_rn(acc[mt][nt][0], acc[mt][nt][1]);
                *reinterpret_cast<__half2*>(g_Th + (size_t)(row + 8) * DD + col) =
                    __floats2half2_rn(acc[mt][nt][2], acc[mt][nt][3]);
            }
    } else if (MODE == 0) {
        // s_ij = (acc + rs_j*c1_i + xak_j*c2_i) * alpha
#pragma unroll
        for (int mt = 0; mt < 4; mt++) {
            const int row = r0 + mt * 16;
            const float c1a = g_c1[row],     c2a = g_c2[row];
            const float c1b = g_c1[row + 8], c2b = g_c2[row + 8];
#pragma unroll
            for (int nt = 0; nt < 4; nt++) {
                const int col = bn + c0 + nt * 8;
                const float rs0 = g_rs[col],  rs1 = g_rs[col + 1];
                const float xk0 = g_xak[col], xk1 = g_xak[col + 1];
                *reinterpret_cast<float2*>(C + (size_t)row * N + col) =
                    make_float2((acc[mt][nt][0] + rs0 * c1a + xk0 * c2a) * alpha,
                                (acc[mt][nt][1] + rs1 * c1a + xk1 * c2a) * alpha);
                *reinterpret_cast<float2*>(C + (size_t)(row + 8) * N + col) =
                    make_float2((acc[mt][nt][2] + rs0 * c1b + xk0 * c2b) * alpha,
                                (acc[mt][nt][3] + rs1 * c1b + xk1 * c2b) * alpha);
            }
        }
    } else {   // MODE 1
#pragma unroll
        for (int mt = 0; mt < 4; mt++)
#pragma unroll
            for (int nt = 0; nt < 4; nt++) {
                const int row = r0 + mt * 16;
                const int col = bn + c0 + nt * 8;
                *reinterpret_cast<float2*>(C + (size_t)row * N + col) =
                    make_float2(acc[mt][nt][0], acc[mt][nt][1]);
                *reinterpret_cast<float2*>(C + (size_t)(row + 8) * N + col) =
                    make_float2(acc[mt][nt][2], acc[mt][nt][3]);
            }
    }
}

// ---------------------------------------------------------------------------
// fused hi/lo fp16 splits: z=0 -> x; z=1 -> Wq-0.5; z=2 -> Wk-0.5
// ---------------------------------------------------------------------------
__global__ __launch_bounds__(256)
void split3_f16(const float* __restrict__ x, const float* __restrict__ wq,
                const float* __restrict__ wk)
{
    const int z = blockIdx.y;
    const float* in = (z == 0) ? x : (z == 1) ? wq : wk;
    __half* hi = (z == 0) ? g_xh : (z == 1) ? g_wh : g_wh + WW;
    __half* lo = (z == 0) ? g_xl : (z == 1) ? g_wl : g_wl + WW;
    const int n = (z == 0) ? NT * DD : DD * DD;
    const float bias = (z == 0) ? 0.0f : 0.5f;

    const int idx = (blockIdx.x * 256 + threadIdx.x) * 2;
    if (idx < n) {
        const float2 v = *reinterpret_cast<const float2*>(in + idx);
        split_store_f16(hi, lo, idx, v.x - bias, v.y - bias);
    }
}

// ---------------------------------------------------------------------------
// fp32 [R,C] -> transposed fp16 [C,R], hi only   (Wv -> Wv^T, V -> V^T)
// ---------------------------------------------------------------------------
__global__ __launch_bounds__(256)
void t_h16(const float* __restrict__ in, __half* __restrict__ oh, int R, int C)
{
    __shared__ float t[32][33];
    const int bx = blockIdx.x * 32, by = blockIdx.y * 32;
    const int tx = threadIdx.x & 31, ty = threadIdx.x >> 5;
#pragma unroll
    for (int j = 0; j < 32; j += 8)
        t[ty + j][tx] = in[(size_t)(by + ty + j) * C + bx + tx];
    __syncthreads();
#pragma unroll
    for (int j = 0; j < 32; j += 8) {
        const float v = t[tx][ty + j];
        oh[(size_t)(bx + ty + j) * R + by + tx] = __float2half_rn(v);
    }
}

// ---------------------------------------------------------------------------
// Correction scalars — fp32 warp-per-row, shuffle reductions.
// ---------------------------------------------------------------------------
__global__ __launch_bounds__(256)
void wrowsums(const float* __restrict__ wq, const float* __restrict__ wk)
{
    const int warp = blockIdx.x * 8 + (threadIdx.x >> 5);   // 0..2047
    const int lane = threadIdx.x & 31;
    const int r = warp & 1023;
    const bool isq = warp < 1024;
    const float* src = (isq ? wq : wk) + (size_t)r * DD;

    float s = 0.0f;
#pragma unroll
    for (int it = 0; it < 8; it++) {
        const float4 v = *reinterpret_cast<const float4*>(src + it * 128 + lane * 4);
        s += (v.x - 0.5f) + (v.y - 0.5f) + (v.z - 0.5f) + (v.w - 0.5f);
    }
#pragma unroll
    for (int o = 16; o > 0; o >>= 1) s += __shfl_xor_sync(0xFFFFFFFFu, s, o);
    if (lane == 0) (isq ? g_aq : g_ak)[r] = s;
}

__global__ __launch_bounds__(256)
void xscalars(const float* __restrict__ x)
{
    if (blockIdx.x < 8) {                       // zero PV flags (2048 ints)
        (&g_flags[0][0])[blockIdx.x * 256 + threadIdx.x] = 0;
    }

    const int warp = blockIdx.x * 8 + (threadIdx.x >> 5);   // 0..4095
    const int lane = threadIdx.x & 31;
    const float* p = x + (size_t)warp * DD;

    float s0 = 0.0f, s1 = 0.0f, s2 = 0.0f;
#pragma unroll
    for (int it = 0; it < 8; it++) {
        const int d = it * 128 + lane * 4;
        const float4 xv = *reinterpret_cast<const float4*>(p + d);
        const float4 aq = *reinterpret_cast<const float4*>(g_aq + d);
        const float4 ak = *reinterpret_cast<const float4*>(g_ak + d);
        s0 += xv.x + xv.y + xv.z + xv.w;
        s1 += xv.x * aq.x + xv.y * aq.y + xv.z * aq.z + xv.w * aq.w;
        s2 += xv.x * ak.x + xv.y * ak.y + xv.z * ak.z + xv.w * ak.w;
    }
#pragma unroll
    for (int o = 16; o > 0; o >>= 1) {
        s0 += __shfl_xor_sync(0xFFFFFFFFu, s0, o);
        s1 += __shfl_xor_sync(0xFFFFFFFFu, s1, o);
        s2 += __shfl_xor_sync(0xFFFFFFFFu, s2, o);
    }
    if (lane == 0) {
        g_rs[warp]  = s0;
        g_xak[warp] = s2;
        g_c1[warp]  = 256.0f * s0 + 0.5f * s1;
        g_c2[warp]  = 0.5f * s0;
    }
}

// ---------------------------------------------------------------------------
// Row softmax over S -> P fp16 (exp-skip) + PV active-chunk flags.
// ---------------------------------------------------------------------------
__global__ __launch_bounds__(256)
void softmax_f16(const float* __restrict__ S, __half* __restrict__ Ph)
{
    const int row = blockIdx.x;
    const float* p = S + (size_t)row * NT;
    const int tid = threadIdx.x;
    const int base = tid * 16;

    float v[16];
#pragma unroll
    for (int q = 0; q < 4; q++) {
        const float4 x4 = *reinterpret_cast<const float4*>(p + base + q * 4);
        v[q * 4 + 0] = x4.x; v[q * 4 + 1] = x4.y; v[q * 4 + 2] = x4.z; v[q * 4 + 3] = x4.w;
    }

    __shared__ float red[256];
    float tmax = v[0];
#pragma unroll
    for (int q = 1; q < 16; q++) tmax = fmaxf(tmax, v[q]);
    red[tid] = tmax;
    __syncthreads();
#pragma unroll
    for (int s = 128; s > 0; s >>= 1) {
        if (tid < s) red[tid] = fmaxf(red[tid], red[tid + s]);
        __syncthreads();
    }
    const float m = red[0];
    __syncthreads();

    const float cut = m - 20.0f;
    const bool active = (tmax >= cut);

    if (active) g_flags[row >> 7][tid >> 2] = 1;   // idempotent; races benign

    float sum = 0.0f;
    if (active) {
#pragma unroll
        for (int q = 0; q < 16; q++) {
            v[q] = (v[q] >= cut) ? __expf(v[q] - m) : 0.0f;
            sum += v[q];
        }
    }
    red[tid] = sum;
    __syncthreads();
#pragma unroll
    for (int s = 128; s > 0; s >>= 1) {
        if (tid < s) red[tid] += red[tid + s];
        __syncthreads();
    }
    const float inv = 1.0f / red[0];

    __half* ph = Ph + (size_t)row * NT + base;
    if (active) {
#pragma unroll
        for (int q = 0; q < 8; q++) {
            *reinterpret_cast<__half2*>(ph + 2 * q) =
                __floats2half2_rn(v[2 * q] * inv, v[2 * q + 1] * inv);
        }
    } else {
        const __half2 z = __floats2half2_rn(0.0f, 0.0f);
#pragma unroll
        for (int q = 0; q < 8; q++)
            *reinterpret_cast<__half2*>(ph + 2 * q) = z;
    }
}

// ---------------------------------------------------------------------------
// Compact PV active-chunk flags into per-row-block lists (padded by 2).
// ---------------------------------------------------------------------------
__global__ __launch_bounds__(32)
void compact_chunks()
{
    const int r = blockIdx.x;
    if (threadIdx.x == 0) {
        int c = 0;
#pragma unroll
        for (int i = 0; i < 64; i++)
            if (g_flags[r][i]) g_chunks[r][c++] = i;
        g_nchunk[r] = c;
        const int pad = g_chunks[r][0];
        g_chunks[r][c] = pad;
        g_chunks[r][c + 1] = pad;
    }
}

// ---------------------------------------------------------------------------
// kernel_launch
// ---------------------------------------------------------------------------
extern "C" void kernel_launch(void* const* d_in, const int* in_sizes, int n_in,
                              void* d_out, int out_size)
{
    const float* x  = (const float*)d_in[0];
    const float* wq = (const float*)d_in[1];
    const float* wk = (const float*)d_in[2];
    const float* wv = (const float*)d_in[3];
    float* out = (float*)d_out;

    float *V, *S;
    __half *xh, *wh, *Th, *MTh, *Vth, *Ph;
    cudaGetSymbolAddress((void**)&V, g_V);
    cudaGetSymbolAddress((void**)&S, g_S);
    cudaGetSymbolAddress((void**)&xh, g_xh);
    cudaGetSymbolAddress((void**)&wh, g_wh);
    cudaGetSymbolAddress((void**)&Th, g_Th);
    cudaGetSymbolAddress((void**)&MTh, g_MTh);
    cudaGetSymbolAddress((void**)&Ph, g_Ph);
    cudaGetSymbolAddress((void**)&Vth, g_xl);   // V^T fp16 reuses g_xl (xl unused)

    static bool attr_done = false;
    if (!attr_done) {
        cudaFuncSetAttribute(gemm_mma<0>, cudaFuncAttributeMaxDynamicSharedMemorySize,
                             3 * 2 * TILE_B);
        cudaFuncSetAttribute(gemm_mma<1>, cudaFuncAttributeMaxDynamicSharedMemorySize,
                             3 * 2 * TILE_B);
        cudaFuncSetAttribute(gemm_mma<2>, cudaFuncAttributeMaxDynamicSharedMemorySize,
                             3 * 3 * TILE_B);
        cudaFuncSetAttribute(gemm_mma<3>, cudaFuncAttributeMaxDynamicSharedMemorySize,
                             3 * 2 * TILE_B);
        attr_done = true;
    }

    const dim3 blk(256);

    // 1) prep: splits + Wv^T hi transpose + correction scalars
    split3_f16<<<dim3(NT * DD / 512, 3), blk>>>(x, wq, wk);
    t_h16<<<dim3(DD / 32, DD / 32), blk>>>(wv, wh + 2 * WW, DD, DD);
    wrowsums<<<256, blk>>>(wq, wk);
    xscalars<<<512, blk>>>(x);

    // 2) fused prep GEMM: V = xh@Wvh^T (fp32) and M~^T = Wkh@W~q^T (2-term)
    gemm_mma<2><<<dim3(DD / 128, NT / 128 + DD / 128), blk, 3 * 3 * TILE_B>>>(
        nullptr, nullptr, nullptr, 0, DD, DD, 1.0f);

    // 3) V^T fp16 (hi only) into g_xl
    t_h16<<<dim3(DD / 32, NT / 32), blk>>>(V, (__half*)Vth, NT, DD);

    // 4) T~ = xh @ M~h  (1 term)
    gemm_mma<3><<<dim3(DD / 128, NT / 128), blk, 3 * 2 * TILE_B>>>(
        xh, MTh, nullptr, NT, DD, DD, 1.0f);

    // 5) scores (dense): S = (Th @ xh^T + rank-2 corr) / 32
    gemm_mma<0><<<dim3(NT / 128, NT / 128), blk, 3 * 2 * TILE_B>>>(
        Th, xh, S, NT, NT, DD, 1.0f / 32.0f);

    // 6) softmax -> P fp16 + PV chunk flags; compact lists
    softmax_f16<<<NT, blk>>>(S, Ph);
    compact_chunks<<<32, 32>>>();

    // 7) out = P @ V   (1-term; SPARSE chunks; occ 2; B = V^T [1024, 4096])
    gemm_mma<1><<<dim3(DD / 128, NT / 128), blk, 3 * 2 * TILE_B>>>(
        Ph, (const __half*)Vth, out, NT, DD, NT, 1.0f);
}

// round 17
// speedup vs baseline: 1.1499x; 1.0070x over previous
#include <cuda_runtime.h>
#include <cuda_fp16.h>
#include <cstdint>

static constexpr int NT = 4096;   // tokens
static constexpr int DD = 1024;   // d_in == d_out
static constexpr size_t WW = (size_t)DD * DD;

// ---------------- scratch (__device__ globals: allocation-free rule) --------
__device__ float g_V[(size_t)NT * DD];              // low 8MB reused as fp16 V
__device__ float g_S[(size_t)NT * NT];              // fp32 scores

__device__ __half g_xh[(size_t)NT * DD], g_xl[(size_t)NT * DD];
// region 0: W~q hi | region 1: W~k hi | region 2: Wv^T hi
__device__ __half g_wh[(size_t)3 * DD * DD];
__device__ __half g_wl[(size_t)2 * DD * DD];        // lo for Wq (used by M), Wk (unused)
__device__ __half g_Th[(size_t)NT * DD];            // T~ = x@M~ (hi only)
__device__ __half g_MTh[(size_t)DD * DD];           // M~^T (hi only)
__device__ __half g_Ph[(size_t)NT * NT];            // P fp16

// rank-2 correction scalars
__device__ float g_aq[DD], g_ak[DD];
__device__ float g_rs[NT], g_xak[NT], g_c1[NT], g_c2[NT];

// exact per-(row, 128-col-block) score maxima (monotone-encoded uint)
__device__ unsigned int g_cmax[(size_t)NT * 32];

// sparse-PV chunk bookkeeping: 32 row-blocks x 64 K-chunks
__device__ int g_flags[32][64];
__device__ int g_chunks[32][66];
__device__ int g_nchunk[32];

// ---------------- helpers ---------------------------------------------------
__device__ __forceinline__ uint32_t smem_u32(const void* p) {
    uint32_t a;
    asm("{ .reg .u64 t; cvta.to.shared.u64 t, %1; cvt.u32.u64 %0, t; }"
        : "=r"(a) : "l"(p));
    return a;
}

#define SWZ(o) ((o) ^ ((((uint32_t)(o)) >> 3) & 0x70))

__device__ __forceinline__ void cp16(uint32_t saddr, const void* gaddr) {
    asm volatile("cp.async.cg.shared.global [%0], [%1], 16;"
                 :: "r"(saddr), "l"(gaddr));
}

__device__ __forceinline__ void ldm_x4(uint32_t* r, uint32_t addr) {
    asm volatile("ldmatrix.sync.aligned.m8n8.x4.shared.b16 {%0,%1,%2,%3}, [%4];"
                 : "=r"(r[0]), "=r"(r[1]), "=r"(r[2]), "=r"(r[3]) : "r"(addr));
}

__device__ __forceinline__ void mma_f16(float* c, const uint32_t* a, const uint32_t* b) {
    asm volatile(
        "mma.sync.aligned.m16n8k16.row.col.f32.f16.f16.f32 "
        "{%0,%1,%2,%3}, {%4,%5,%6,%7}, {%8,%9}, {%0,%1,%2,%3};"
        : "+f"(c[0]), "+f"(c[1]), "+f"(c[2]), "+f"(c[3])
        : "r"(a[0]), "r"(a[1]), "r"(a[2]), "r"(a[3]), "r"(b[0]), "r"(b[1]));
}

__device__ __forceinline__ void split_store_f16(
    __half* H, __half* L, size_t idx, float a, float b)
{
    const __half h0 = __float2half_rn(a);
    const __half h1 = __float2half_rn(b);
    const __half l0 = __float2half_rn(a - __half2float(h0));
    const __half l1 = __float2half_rn(b - __half2float(h1));
    *reinterpret_cast<__half2*>(H + idx) = __halves2half2(h0, h1);
    *reinterpret_cast<__half2*>(L + idx) = __halves2half2(l0, l1);
}

// monotone float <-> uint encoding (order-preserving under unsigned compare)
__device__ __forceinline__ unsigned int enc_f(float f) {
    const unsigned int u = __float_as_uint(f);
    return (u & 0x80000000u) ? ~u : (u ^ 0x80000000u);
}
__device__ __forceinline__ float dec_f(unsigned int k) {
    return __uint_as_float((k & 0x80000000u) ? (k ^ 0x80000000u) : ~k);
}

// ---------------------------------------------------------------------------
// Warp-MMA fp16 GEMM, BK=64, 3-stage cp.async pipeline.
//  MODE 0 (scores): S = Th@xh^T (1 term, dense); occ 2;
//                   epilogue adds rank-2 corr, scales, records per-(row,
//                   128-col-block) exact maxima into g_cmax via atomicMax.
//  MODE 1 (PV):     C = Ph@Vth^T, 1 term, SPARSE over active K-chunks; occ 2.
//  MODE 2 (prep, fused grid; occ 1; tiles {A0,B0,B1}):
//     by <  32: V = xh @ Wvh^T (1 term) -> fp16 row-major into g_V
//     by >= 32: M~^T = Wkh @ (Wqh + Wql)^T (2 terms) -> g_MTh (hi only)
//  MODE 3 (T):      T~ = xh@M~h (1 term) -> g_Th; occ 2.
// BM=BN=128, BK=64, 256 threads, 2(m)x4(n) warps, 64x32 warp tile.
// ---------------------------------------------------------------------------
static constexpr int TILE_B = 128 * 128;   // 16 KB (128 rows x 64 fp16)

template <int MODE>
__global__ __launch_bounds__(256, (MODE == 2) ? 1 : 2)
void gemm_mma(const __half* __restrict__ A0, const __half* __restrict__ B0,
              float* __restrict__ C, int M, int N, int K, float alpha)
{
    constexpr int NTILES  = (MODE == 2) ? 3 : 2;
    constexpr int STAGE_B = NTILES * TILE_B;

    extern __shared__ char smem[];
    const uint32_t sb = smem_u32(smem);
    const int tid  = threadIdx.x;
    const int wid  = tid >> 5;
    const int lane = tid & 31;

    const bool isM = (MODE == 2) && (blockIdx.y >= 32);   // M~^T region of prep
    const int bm = (MODE == 2 && isM) ? (blockIdx.y - 32) * 128 : blockIdx.y * 128;
    const int bn = blockIdx.x * 128;
    const int wm = (wid >> 2) * 64;
    const int wn = (wid & 3) * 32;

    const bool useB1 = (MODE == 2) && isM;   // a0*b1 term (M region only)

    const __half* srcs[3];
    int rbs[3];
    if (MODE == 2) {
        if (isM) {      // A0 = Wk hi, B0 = Wq hi, B1 = Wq lo (all centered)
            srcs[0] = g_wh + WW; srcs[1] = g_wh;          srcs[2] = g_wl;
        } else {        // A0 = xh, B0 = Wv^T hi
            srcs[0] = g_xh;      srcs[1] = g_wh + 2 * WW; srcs[2] = nullptr;
        }
        rbs[0] = bm; rbs[1] = bn; rbs[2] = bn;
    } else {
        srcs[0] = A0; rbs[0] = bm;
        srcs[1] = B0; rbs[1] = bn;
        srcs[2] = nullptr; rbs[2] = 0;
    }

    auto issue = [&](int stage, int kchunk) {
#pragma unroll
        for (int t = 0; t < NTILES; t++) {
            if (MODE == 2 && !isM && t == 2) continue;   // V region: no B1 tile
#pragma unroll
            for (int u = 0; u < 4; u++) {
                const int v = tid + 256 * u;            // 0..1023
                const int row = v >> 3, c16 = v & 7;
                const uint32_t o = (uint32_t)(row * 128 + c16 * 16);
                cp16(sb + stage * STAGE_B + t * TILE_B + SWZ(o),
                     srcs[t] + (size_t)(rbs[t] + row) * K + kchunk * 64 + c16 * 8);
            }
        }
        asm volatile("cp.async.commit_group;");
    };

    float acc[4][4][4];
#pragma unroll
    for (int i = 0; i < 4; i++)
#pragma unroll
        for (int j = 0; j < 4; j++)
#pragma unroll
            for (int r = 0; r < 4; r++) acc[i][j][r] = 0.0f;

    // chunk schedule: MODE 1 uses the sparse per-row-block list; others dense
    const int* cl = (MODE == 1) ? g_chunks[blockIdx.y] : nullptr;
    const int nc  = (MODE == 1) ? g_nchunk[blockIdx.y] : K / 64;

    issue(0, (MODE == 1) ? cl[0] : 0);
    issue(1, (MODE == 1) ? cl[1] : 1);

    const int arow   = lane & 15;
    const int achunk = lane >> 4;
    const int bsub   = lane >> 3;
    const int brow   = (lane & 7) + (bsub >> 1) * 8;
    const int bchunk = bsub & 1;

    for (int i = 0; i < nc; i++) {
        if (i < nc - 1) asm volatile("cp.async.wait_group 1;");
        else            asm volatile("cp.async.wait_group 0;");
        __syncthreads();

        if (i + 2 < nc) issue((i + 2) % 3, (MODE == 1) ? cl[i + 2] : i + 2);

        const uint32_t base = sb + (i % 3) * STAGE_B;
#pragma unroll
        for (int s = 0; s < 4; s++) {                  // 4 x k16 per BK=64 chunk
            uint32_t a0[4][4], b0r[4][2], b1r[4][2];
#pragma unroll
            for (int t = 0; t < 4; t++) {
                const uint32_t o =
                    (uint32_t)((wm + t * 16 + arow) * 128 + (s * 2 + achunk) * 16);
                ldm_x4(a0[t], base + SWZ(o));
            }
#pragma unroll
            for (int g = 0; g < 2; g++) {
                const uint32_t o =
                    (uint32_t)((wn + g * 16 + brow) * 128 + (s * 2 + bchunk) * 16);
                uint32_t r[4];
                ldm_x4(r, base + 1 * TILE_B + SWZ(o));
                b0r[2 * g][0] = r[0]; b0r[2 * g][1] = r[1];
                b0r[2 * g + 1][0] = r[2]; b0r[2 * g + 1][1] = r[3];
                if (useB1) {
                    ldm_x4(r, base + 2 * TILE_B + SWZ(o));
                    b1r[2 * g][0] = r[0]; b1r[2 * g][1] = r[1];
                    b1r[2 * g + 1][0] = r[2]; b1r[2 * g + 1][1] = r[3];
                }
            }
#pragma unroll
            for (int mt = 0; mt < 4; mt++)
#pragma unroll
                for (int nt = 0; nt < 4; nt++) {
                    mma_f16(acc[mt][nt], a0[mt], b0r[nt]);
                    if (useB1) mma_f16(acc[mt][nt], a0[mt], b1r[nt]);
                }
        }
    }

    // ---- epilogue ----
    const int r0 = bm + wm + (lane >> 2);
    const int c0 = wn + (lane & 3) * 2;

    if (MODE == 2) {
#pragma unroll
        for (int mt = 0; mt < 4; mt++)
#pragma unroll
            for (int nt = 0; nt < 4; nt++) {
                const int row = r0 + mt * 16;
                const int col = bn + c0 + nt * 8;
                const size_t i0 = (size_t)row * DD + col;
                const size_t i1 = (size_t)(row + 8) * DD + col;
                if (isM) {
                    *reinterpret_cast<__half2*>(g_MTh + i0) =
                        __floats2half2_rn(acc[mt][nt][0], acc[mt][nt][1]);
                    *reinterpret_cast<__half2*>(g_MTh + i1) =
                        __floats2half2_rn(acc[mt][nt][2], acc[mt][nt][3]);
                } else {
                    __half* Vh = reinterpret_cast<__half*>(g_V);
                    *reinterpret_cast<__half2*>(Vh + i0) =
                        __floats2half2_rn(acc[mt][nt][0], acc[mt][nt][1]);
                    *reinterpret_cast<__half2*>(Vh + i1) =
                        __floats2half2_rn(acc[mt][nt][2], acc[mt][nt][3]);
                }
            }
    } else if (MODE == 3) {
#pragma unroll
        for (int mt = 0; mt < 4; mt++)
#pragma unroll
            for (int nt = 0; nt < 4; nt++) {
                const int row = r0 + mt * 16;
                const int col = bn + c0 + nt * 8;
                *reinterpret_cast<__half2*>(g_Th + (size_t)row * DD + col) =
                    __floats2half2_rn(acc[mt][nt][0], acc[mt][nt][1]);
                *reinterpret_cast<__half2*>(g_Th + (size_t)(row + 8) * DD + col) =
                    __floats2half2_rn(acc[mt][nt][2], acc[mt][nt][3]);
            }
    } else if (MODE == 0) {
        // s_ij = (acc + rs_j*c1_i + xak_j*c2_i) * alpha ; record block maxima
#pragma unroll
        for (int mt = 0; mt < 4; mt++) {
            const int row = r0 + mt * 16;
            const float c1a = g_c1[row],     c2a = g_c2[row];
            const float c1b = g_c1[row + 8], c2b = g_c2[row + 8];
            float mxA = -3e38f, mxB = -3e38f;
#pragma unroll
            for (int nt = 0; nt < 4; nt++) {
                const int col = bn + c0 + nt * 8;
                const float rs0 = g_rs[col],  rs1 = g_rs[col + 1];
                const float xk0 = g_xak[col], xk1 = g_xak[col + 1];
                const float v0 = (acc[mt][nt][0] + rs0 * c1a + xk0 * c2a) * alpha;
                const float v1 = (acc[mt][nt][1] + rs1 * c1a + xk1 * c2a) * alpha;
                const float v2 = (acc[mt][nt][2] + rs0 * c1b + xk0 * c2b) * alpha;
                const float v3 = (acc[mt][nt][3] + rs1 * c1b + xk1 * c2b) * alpha;
                *reinterpret_cast<float2*>(C + (size_t)row * N + col) =
                    make_float2(v0, v1);
                *reinterpret_cast<float2*>(C + (size_t)(row + 8) * N + col) =
                    make_float2(v2, v3);
                mxA = fmaxf(mxA, fmaxf(v0, v1));
                mxB = fmaxf(mxB, fmaxf(v2, v3));
            }
            // reduce over the 4 lanes (lane&3) covering this row's 32 cols
            mxA = fmaxf(mxA, __shfl_xor_sync(0xFFFFFFFFu, mxA, 1));
            mxA = fmaxf(mxA, __shfl_xor_sync(0xFFFFFFFFu, mxA, 2));
            mxB = fmaxf(mxB, __shfl_xor_sync(0xFFFFFFFFu, mxB, 1));
            mxB = fmaxf(mxB, __shfl_xor_sync(0xFFFFFFFFu, mxB, 2));
            if ((lane & 3) == 0) {
                atomicMax(&g_cmax[(size_t)row * 32 + blockIdx.x], enc_f(mxA));
                atomicMax(&g_cmax[(size_t)(row + 8) * 32 + blockIdx.x], enc_f(mxB));
            }
        }
    } else {   // MODE 1
#pragma unroll
        for (int mt = 0; mt < 4; mt++)
#pragma unroll
            for (int nt = 0; nt < 4; nt++) {
                const int row = r0 + mt * 16;
                const int col = bn + c0 + nt * 8;
                *reinterpret_cast<float2*>(C + (size_t)row * N + col) =
                    make_float2(acc[mt][nt][0], acc[mt][nt][1]);
                *reinterpret_cast<float2*>(C + (size_t)(row + 8) * N + col) =
                    make_float2(acc[mt][nt][2], acc[mt][nt][3]);
            }
    }
}

// ---------------------------------------------------------------------------
// fused hi/lo fp16 splits: z=0 -> x; z=1 -> Wq-0.5; z=2 -> Wk-0.5
// ---------------------------------------------------------------------------
__global__ __launch_bounds__(256)
void split3_f16(const float* __restrict__ x, const float* __restrict__ wq,
                const float* __restrict__ wk)
{
    const int z = blockIdx.y;
    const float* in = (z == 0) ? x : (z == 1) ? wq : wk;
    __half* hi = (z == 0) ? g_xh : (z == 1) ? g_wh : g_wh + WW;
    __half* lo = (z == 0) ? g_xl : (z == 1) ? g_wl : g_wl + WW;
    const int n = (z == 0) ? NT * DD : DD * DD;
    const float bias = (z == 0) ? 0.0f : 0.5f;

    const int idx = (blockIdx.x * 256 + threadIdx.x) * 2;
    if (idx < n) {
        const float2 v = *reinterpret_cast<const float2*>(in + idx);
        split_store_f16(hi, lo, idx, v.x - bias, v.y - bias);
    }
}

// ---------------------------------------------------------------------------
// fp32 [R,C] -> transposed fp16 [C,R], hi only   (Wv -> Wv^T)
// ---------------------------------------------------------------------------
__global__ __launch_bounds__(256)
void t_h16(const float* __restrict__ in, __half* __restrict__ oh, int R, int C)
{
    __shared__ float t[32][33];
    const int bx = blockIdx.x * 32, by = blockIdx.y * 32;
    const int tx = threadIdx.x & 31, ty = threadIdx.x >> 5;
#pragma unroll
    for (int j = 0; j < 32; j += 8)
        t[ty + j][tx] = in[(size_t)(by + ty + j) * C + bx + tx];
    __syncthreads();
#pragma unroll
    for (int j = 0; j < 32; j += 8) {
        const float v = t[tx][ty + j];
        oh[(size_t)(bx + ty + j) * R + by + tx] = __float2half_rn(v);
    }
}

// ---------------------------------------------------------------------------
// fp16 [R,C] -> transposed fp16 [C,R]   (V fp16 -> V^T fp16)
// ---------------------------------------------------------------------------
__global__ __launch_bounds__(256)
void t_h16h(const __half* __restrict__ in, __half* __restrict__ oh, int R, int C)
{
    __shared__ __half t[32][34];
    const int bx = blockIdx.x * 32, by = blockIdx.y * 32;
    const int tx = threadIdx.x & 31, ty = threadIdx.x >> 5;
#pragma unroll
    for (int j = 0; j < 32; j += 8)
        t[ty + j][tx] = in[(size_t)(by + ty + j) * C + bx + tx];
    __syncthreads();
#pragma unroll
    for (int j = 0; j < 32; j += 8)
        oh[(size_t)(bx + ty + j) * R + by + tx] = t[tx][ty + j];
}

// ---------------------------------------------------------------------------
// Correction scalars — fp32 warp-per-row, shuffle reductions.
// ---------------------------------------------------------------------------
__global__ __launch_bounds__(256)
void wrowsums(const float* __restrict__ wq, const float* __restrict__ wk)
{
    const int warp = blockIdx.x * 8 + (threadIdx.x >> 5);   // 0..2047
    const int lane = threadIdx.x & 31;
    const int r = warp & 1023;
    const bool isq = warp < 1024;
    const float* src = (isq ? wq : wk) + (size_t)r * DD;

    float s = 0.0f;
#pragma unroll
    for (int it = 0; it < 8; it++) {
        const float4 v = *reinterpret_cast<const float4*>(src + it * 128 + lane * 4);
        s += (v.x - 0.5f) + (v.y - 0.5f) + (v.z - 0.5f) + (v.w - 0.5f);
    }
#pragma unroll
    for (int o = 16; o > 0; o >>= 1) s += __shfl_xor_sync(0xFFFFFFFFu, s, o);
    if (lane == 0) (isq ? g_aq : g_ak)[r] = s;
}

__global__ __launch_bounds__(256)
void xscalars(const float* __restrict__ x)
{
    // zero g_cmax (131072 uints; one per thread across the 512-block grid)
    g_cmax[(size_t)blockIdx.x * 256 + threadIdx.x] = 0u;
    if (blockIdx.x < 8) {                       // zero PV flags (2048 ints)
        (&g_flags[0][0])[blockIdx.x * 256 + threadIdx.x] = 0;
    }

    const int warp = blockIdx.x * 8 + (threadIdx.x >> 5);   // 0..4095
    const int lane = threadIdx.x & 31;
    const float* p = x + (size_t)warp * DD;

    float s0 = 0.0f, s1 = 0.0f, s2 = 0.0f;
#pragma unroll
    for (int it = 0; it < 8; it++) {
        const int d = it * 128 + lane * 4;
        const float4 xv = *reinterpret_cast<const float4*>(p + d);
        const float4 aq = *reinterpret_cast<const float4*>(g_aq + d);
        const float4 ak = *reinterpret_cast<const float4*>(g_ak + d);
        s0 += xv.x + xv.y + xv.z + xv.w;
        s1 += xv.x * aq.x + xv.y * aq.y + xv.z * aq.z + xv.w * aq.w;
        s2 += xv.x * ak.x + xv.y * ak.y + xv.z * ak.z + xv.w * ak.w;
    }
#pragma unroll
    for (int o = 16; o > 0; o >>= 1) {
        s0 += __shfl_xor_sync(0xFFFFFFFFu, s0, o);
        s1 += __shfl_xor_sync(0xFFFFFFFFu, s1, o);
        s2 += __shfl_xor_sync(0xFFFFFFFFu, s2, o);
    }
    if (lane == 0) {
        g_rs[warp]  = s0;
        g_xak[warp] = s2;
        g_c1[warp]  = 256.0f * s0 + 0.5f * s1;
        g_c2[warp]  = 0.5f * s0;
    }
}

// ---------------------------------------------------------------------------
// Row softmax -> P fp16, driven by exact per-block maxima (g_cmax):
// row max = max of 32 cmax entries (no S read); only blocks with
// cmax >= max-20 are loaded; skipped blocks produce the same zeros the
// per-element exp-skip would have. Sets PV active-chunk flags.
// ---------------------------------------------------------------------------
__global__ __launch_bounds__(256)
void softmax_f16(const float* __restrict__ S, __half* __restrict__ Ph)
{
    const int row = blockIdx.x;
    const float* p = S + (size_t)row * NT;
    const int tid = threadIdx.x;
    const int base = tid * 16;

    __shared__ float scm[32];
    __shared__ float red[256];
    if (tid < 32) scm[tid] = dec_f(g_cmax[(size_t)row * 32 + tid]);
    __syncthreads();

    float m = scm[0];
#pragma unroll
    for (int k = 1; k < 32; k++) m = fmaxf(m, scm[k]);
    const float cut = m - 20.0f;
    const bool blkAct = (scm[tid >> 3] >= cut);

    float v[16];
    bool active = false;
    float sum = 0.0f;
    if (blkAct) {
#pragma unroll
        for (int q = 0; q < 4; q++) {
            const float4 x4 = *reinterpret_cast<const float4*>(p + base + q * 4);
            v[q * 4 + 0] = x4.x; v[q * 4 + 1] = x4.y;
            v[q * 4 + 2] = x4.z; v[q * 4 + 3] = x4.w;
        }
        float tmax = v[0];
#pragma unroll
        for (int q = 1; q < 16; q++) tmax = fmaxf(tmax, v[q]);
        active = (tmax >= cut);
        if (active) {
            g_flags[row >> 7][tid >> 2] = 1;   // idempotent; races benign
#pragma unroll
            for (int q = 0; q < 16; q++) {
                v[q] = (v[q] >= cut) ? __expf(v[q] - m) : 0.0f;
                sum += v[q];
            }
        }
    }
    red[tid] = sum;
    __syncthreads();
#pragma unroll
    for (int s = 128; s > 0; s >>= 1) {
        if (tid < s) red[tid] += red[tid + s];
        __syncthreads();
    }
    const float inv = 1.0f / red[0];

    __half* ph = Ph + (size_t)row * NT + base;
    if (active) {
#pragma unroll
        for (int q = 0; q < 8; q++) {
            *reinterpret_cast<__half2*>(ph + 2 * q) =
                __floats2half2_rn(v[2 * q] * inv, v[2 * q + 1] * inv);
        }
    } else {
        const __half2 z = __floats2half2_rn(0.0f, 0.0f);
#pragma unroll
        for (int q = 0; q < 8; q++)
            *reinterpret_cast<__half2*>(ph + 2 * q) = z;
    }
}

// ---------------------------------------------------------------------------
// Compact PV active-chunk flags into per-row-block lists (padded by 2).
// ---------------------------------------------------------------------------
__global__ __launch_bounds__(32)
void compact_chunks()
{
    const int r = blockIdx.x;
    if (threadIdx.x == 0) {
        int c = 0;
#pragma unroll
        for (int i = 0; i < 64; i++)
            if (g_flags[r][i]) g_chunks[r][c++] = i;
        g_nchunk[r] = c;
        const int pad = g_chunks[r][0];
        g_chunks[r][c] = pad;
        g_chunks[r][c + 1] = pad;
    }
}

// ---------------------------------------------------------------------------
// kernel_launch
// ---------------------------------------------------------------------------
extern "C" void kernel_launch(void* const* d_in, const int* in_sizes, int n_in,
                              void* d_out, int out_size)
{
    const float* x  = (const float*)d_in[0];
    const float* wq = (const float*)d_in[1];
    const float* wk = (const float*)d_in[2];
    const float* wv = (const float*)d_in[3];
    float* out = (float*)d_out;

    float *V, *S;
    __half *xh, *wh, *Th, *MTh, *Vth, *Ph;
    cudaGetSymbolAddress((void**)&V, g_V);
    cudaGetSymbolAddress((void**)&S, g_S);
    cudaGetSymbolAddress((void**)&xh, g_xh);
    cudaGetSymbolAddress((void**)&wh, g_wh);
    cudaGetSymbolAddress((void**)&Th, g_Th);
    cudaGetSymbolAddress((void**)&MTh, g_MTh);
    cudaGetSymbolAddress((void**)&Ph, g_Ph);
    cudaGetSymbolAddress((void**)&Vth, g_xl);   // V^T fp16 reuses g_xl (xl unused)

    static bool attr_done = false;
    if (!attr_done) {
        cudaFuncSetAttribute(gemm_mma<0>, cudaFuncAttributeMaxDynamicSharedMemorySize,
                             3 * 2 * TILE_B);
        cudaFuncSetAttribute(gemm_mma<1>, cudaFuncAttributeMaxDynamicSharedMemorySize,
                             3 * 2 * TILE_B);
        cudaFuncSetAttribute(gemm_mma<2>, cudaFuncAttributeMaxDynamicSharedMemorySize,
                             3 * 3 * TILE_B);
        cudaFuncSetAttribute(gemm_mma<3>, cudaFuncAttributeMaxDynamicSharedMemorySize,
                             3 * 2 * TILE_B);
        attr_done = true;
    }

    const dim3 blk(256);

    // 1) prep: splits + Wv^T hi transpose + correction scalars (+cmax zero)
    split3_f16<<<dim3(NT * DD / 512, 3), blk>>>(x, wq, wk);
    t_h16<<<dim3(DD / 32, DD / 32), blk>>>(wv, wh + 2 * WW, DD, DD);
    wrowsums<<<256, blk>>>(wq, wk);
    xscalars<<<512, blk>>>(x);

    // 2) fused prep GEMM: V = xh@Wvh^T (fp16 rowmajor) + M~^T (2-term)
    gemm_mma<2><<<dim3(DD / 128, NT / 128 + DD / 128), blk, 3 * 3 * TILE_B>>>(
        nullptr, nullptr, nullptr, 0, DD, DD, 1.0f);

    // 3) V^T fp16: transpose the fp16 V (in g_V) into g_xl
    t_h16h<<<dim3(DD / 32, NT / 32), blk>>>(
        (const __half*)V, (__half*)Vth, NT, DD);

    // 4) T~ = xh @ M~h  (1 term)
    gemm_mma<3><<<dim3(DD / 128, NT / 128), blk, 3 * 2 * TILE_B>>>(
        xh, MTh, nullptr, NT, DD, DD, 1.0f);

    // 5) scores (dense): S = (Th @ xh^T + rank-2 corr) / 32, records g_cmax
    gemm_mma<0><<<dim3(NT / 128, NT / 128), blk, 3 * 2 * TILE_B>>>(
        Th, xh, S, NT, NT, DD, 1.0f / 32.0f);

    // 6) softmax (cmax-driven sparse read) -> P fp16 + PV flags; compact
    softmax_f16<<<NT, blk>>>(S, Ph);
    compact_chunks<<<32, 32>>>();

    // 7) out = P @ V   (1-term; SPARSE chunks; occ 2; B = V^T [1024, 4096])
    gemm_mma<1><<<dim3(DD / 128, NT / 128), blk, 3 * 2 * TILE_B>>>(
        Ph, (const __half*)Vth, out, NT, DD, NT, 1.0f);
}